// round 16
// baseline (speedup 1.0000x reference)
#include <cuda_runtime.h>

// Problem constants (fixed by reference setup_inputs: B=2, N=1024, K=64, R=0.15)
#define NPTS   1024
#define NBATCH 2
#define NQ     (NBATCH * NPTS)     // 2048 queries
#define KNB    64
#define RADIUS2 0.0225f
#define NVAR   10                  // distinct nonzero diag variants

// Static device scratch (no allocation allowed)
__device__ float g_gp[NQ * 3 * KNB];        // SoA relative coords, zero-padded: [q][xyz][64]
__device__ int   g_cnt[NQ];                 // in-ball neighbor count per query
__device__ float g_m[NVAR * NQ * 64];       // per-variant per-query max, 64 ch

// diag variants: 4 full (weight 1 in combine), 6 single-axis (weight 2)
__device__ const float c_DX[NVAR] = { 1.f, 1.f,-1.f,-1.f,  1.f,-1.f, 0.f, 0.f, 0.f, 0.f };
__device__ const float c_DY[NVAR] = { 1.f,-1.f, 1.f,-1.f,  0.f, 0.f, 1.f,-1.f, 0.f, 0.f };
__device__ const float c_DZ[NVAR] = { 1.f,-1.f,-1.f, 1.f,  0.f, 0.f, 0.f, 0.f, 1.f,-1.f };

// ---- packed f32x2 helpers (Blackwell FFMA2: only reachable via PTX) -------
__device__ __forceinline__ unsigned long long ffma2(unsigned long long a,
                                                    unsigned long long b,
                                                    unsigned long long c) {
    unsigned long long d;
    asm("fma.rn.f32x2 %0, %1, %2, %3;" : "=l"(d) : "l"(a), "l"(b), "l"(c));
    return d;
}
__device__ __forceinline__ unsigned long long pack2(float lo, float hi) {
    unsigned long long d;
    asm("mov.b64 %0, {%1, %2};" : "=l"(d) : "f"(lo), "f"(hi));
    return d;
}
__device__ __forceinline__ float2 unpack2(unsigned long long v) {
    float lo, hi;
    asm("mov.b64 {%0, %1}, %2;" : "=f"(lo), "=f"(hi) : "l"(v));
    return make_float2(lo, hi);
}

// ---------------------------------------------------------------------------
// Kernel 1: ball gather — warp per query, ballot compaction (unchanged, 11.6us).
// ---------------------------------------------------------------------------
__global__ void __launch_bounds__(256) gather_kernel(const float* __restrict__ x) {
    __shared__ float ysx[NPTS], ysy[NPTS], ysz[NPTS];
    int warp = threadIdx.x >> 5;
    int lane = threadIdx.x & 31;
    int q = blockIdx.x * 8 + warp;          // 256 blocks x 8 warps = 2048 queries
    int b = q >> 10;                        // all 8 warps of a block share batch
    const float* xb = x + b * NPTS * 3;
    for (int i = threadIdx.x; i < NPTS; i += 256) {
        ysx[i] = xb[i * 3 + 0];
        ysy[i] = xb[i * 3 + 1];
        ysz[i] = xb[i * 3 + 2];
    }
    __syncthreads();

    int n = q & 1023;
    float qx = ysx[n], qy = ysy[n], qz = ysz[n];
    float* gq = g_gp + q * (3 * KNB);

    int base = 0;
    for (int m0 = 0; m0 < NPTS; m0 += 32) {
        int m = m0 + lane;
        float dx = ysx[m] - qx;
        float dy = ysy[m] - qy;
        float dz = ysz[m] - qz;
        // match XLA rounding at the radius boundary: no FMA contraction
        float d2 = __fadd_rn(__fadd_rn(__fmul_rn(dx, dx), __fmul_rn(dy, dy)),
                             __fmul_rn(dz, dz));
        bool hit = (d2 <= RADIUS2);
        unsigned bal = __ballot_sync(0xffffffffu, hit);
        int pos = base + __popc(bal & ((1u << lane) - 1u));
        if (hit && pos < KNB) {
            gq[pos]           = dx;
            gq[KNB + pos]     = dy;
            gq[2 * KNB + pos] = dz;
        }
        base += __popc(bal);
    }
    int cnt = base < KNB ? base : KNB;
    for (int t = cnt + lane; t < KNB; t += 32) {
        gq[t] = 0.0f; gq[KNB + t] = 0.0f; gq[2 * KNB + t] = 0.0f;
    }

    if (base > KNB && lane == 0) {
        // exact rare path: keep the 64 smallest d2 (never fires on this data)
        float dds[KNB];
        int c = 0;
        for (int m = 0; m < NPTS; m++) {
            float dx = ysx[m] - qx, dy = ysy[m] - qy, dz = ysz[m] - qz;
            float d2 = __fadd_rn(__fadd_rn(__fmul_rn(dx, dx), __fmul_rn(dy, dy)),
                                 __fmul_rn(dz, dz));
            if (d2 <= RADIUS2) {
                if (c < KNB) {
                    dds[c] = d2;
                    gq[c] = dx; gq[KNB + c] = dy; gq[2 * KNB + c] = dz;
                    c++;
                } else {
                    float mx = -1.0f; int mi = 0;
                    for (int t = 0; t < KNB; t++)
                        if (dds[t] > mx) { mx = dds[t]; mi = t; }
                    if (d2 < mx) {
                        dds[mi] = d2;
                        gq[mi] = dx; gq[KNB + mi] = dy; gq[2 * KNB + mi] = dz;
                    }
                }
            }
        }
    }
    if (lane == 0) g_cnt[q] = cnt;
}

// ---------------------------------------------------------------------------
// Kernel 2: per-(query, variant, half) MLP + neighbor max.
// One warp per (q, v, half): lane owns ONE output channel o = half*32 + lane.
// Phase 1 (lane = neighbor): h1[32] -> smem row. Phase 2 (lane = channel):
// per neighbor, 8x LDS.128 broadcast of h1 + 16 FFMA2 in 2 chains of 8.
// Half the W2 register footprint of R14 -> ~6 warps/SMSP to hide LDS latency.
// ---------------------------------------------------------------------------
__global__ void __launch_bounds__(256, 3) mlp_kernel(const float* __restrict__ W1,
                                                     const float* __restrict__ b1,
                                                     const float* __restrict__ W2,
                                                     const float* __restrict__ b2) {
    __shared__ float4 sW1f4[32];                         // (w0,w1,w2,b1) per ch
    __shared__ __align__(16) float h1s[8][32][36];       // [warp][nbr][ch], padded

    int tid  = threadIdx.x;
    int lane = tid & 31;
    int wid  = tid >> 5;

    if (tid < 32)
        sW1f4[tid] = make_float4(W1[tid * 3 + 0], W1[tid * 3 + 1],
                                 W1[tid * 3 + 2], b1[tid]);
    __syncthreads();

    int w = blockIdx.x * 8 + wid;        // 0 .. 40959
    int e = w >> 1;                      // (q, v) group
    int half = w & 1;
    int q = e / NVAR;
    int v = e - q * NVAR;
    float sx = c_DX[v], sy = c_DY[v], sz = c_DZ[v];

    // W2 row for output channel o, as packed (c, c+1) pairs: 16 ull = 32 regs.
    int o = half * 32 + lane;
    unsigned long long w2p[16];
    {
        const ulonglong2* p = reinterpret_cast<const ulonglong2*>(W2 + o * 32);
#pragma unroll
        for (int i = 0; i < 8; i++) {
            ulonglong2 t = p[i];
            w2p[2 * i]     = t.x;
            w2p[2 * i + 1] = t.y;
        }
    }
    const unsigned long long biasp = pack2(b2[o], 0.0f);

    int cnt = g_cnt[q];
    const float* gq = g_gp + q * (3 * KNB);
    float (*hrow)[36] = h1s[wid];

    float m = 0.0f;                      // relu outputs >= 0; self in set

    for (int j0 = 0; j0 < cnt; j0 += 32) {
        // ---- phase 1: lane = neighbor (g_gp zero-padded, safe to read < 64)
        int jj = j0 + lane;
        float px = sx * gq[jj];
        float py = sy * gq[KNB + jj];
        float pz = sz * gq[2 * KNB + jj];
#pragma unroll
        for (int c = 0; c < 32; c += 4) {
            float4 hv;
            float4 w0 = sW1f4[c + 0];
            hv.x = fmaxf(fmaf(px, w0.x, fmaf(py, w0.y, fmaf(pz, w0.z, w0.w))), 0.0f);
            float4 w1r = sW1f4[c + 1];
            hv.y = fmaxf(fmaf(px, w1r.x, fmaf(py, w1r.y, fmaf(pz, w1r.z, w1r.w))), 0.0f);
            float4 w2r = sW1f4[c + 2];
            hv.z = fmaxf(fmaf(px, w2r.x, fmaf(py, w2r.y, fmaf(pz, w2r.z, w2r.w))), 0.0f);
            float4 w3r = sW1f4[c + 3];
            hv.w = fmaxf(fmaf(px, w3r.x, fmaf(py, w3r.y, fmaf(pz, w3r.z, w3r.w))), 0.0f);
            *reinterpret_cast<float4*>(&hrow[lane][c]) = hv;
        }
        __syncwarp();

        // ---- phase 2: lane = output channel; iterate real neighbors only
        int jend = cnt - j0; if (jend > 32) jend = 32;
        for (int j = 0; j < jend; j++) {
            const ulonglong2* hp = reinterpret_cast<const ulonglong2*>(&hrow[j][0]);
            unsigned long long accA = biasp, accB = 0ull;
#pragma unroll
            for (int i = 0; i < 8; i++) {
                ulonglong2 h = hp[i];          // h pairs (4i,4i+1), (4i+2,4i+3)
                accA = ffma2(h.x, w2p[2 * i],     accA);
                accB = ffma2(h.y, w2p[2 * i + 1], accB);
            }
            float2 sA = unpack2(accA), sB = unpack2(accB);
            float r = (sA.x + sA.y) + (sB.x + sB.y);
            m = fmaxf(m, fmaxf(r, 0.0f));
        }
        __syncwarp();
    }

    g_m[(v * NQ + q) * 64 + o] = m;
}

// ---------------------------------------------------------------------------
// Kernel 3: combine. f[b,o,n] = (8*c0[o] + sum_v w_v * m[v,q,o]) / 24
// c0 = relu(W2 relu(b1) + b2): output of the 8 zero-diagonal rotations.
// ---------------------------------------------------------------------------
__global__ void __launch_bounds__(256) combine_kernel(const float* __restrict__ b1,
                                                      const float* __restrict__ W2,
                                                      const float* __restrict__ b2,
                                                      float* __restrict__ out) {
    __shared__ float h1b[32];
    __shared__ float c0s[64];
    int tid = threadIdx.x;
    if (tid < 32) h1b[tid] = fmaxf(b1[tid], 0.0f);
    __syncthreads();
    if (tid < 64) {
        float a = b2[tid];
#pragma unroll
        for (int c = 0; c < 32; c++) a = fmaf(W2[tid * 32 + c], h1b[c], a);
        c0s[tid] = 8.0f * fmaxf(a, 0.0f);
    }
    __syncthreads();

    const float WV[NVAR] = { 1.f, 1.f, 1.f, 1.f, 2.f, 2.f, 2.f, 2.f, 2.f, 2.f };

    int i = blockIdx.x * 256 + tid;      // 0 .. 131071 (= NQ*64)
    int q = i >> 6;
    int o = i & 63;
    float f = c0s[o];
#pragma unroll
    for (int v = 0; v < NVAR; v++)
        f += WV[v] * g_m[(v * NQ + q) * 64 + o];

    int b = q >> 10;
    int n = q & 1023;
    out[(b * 64 + o) * NPTS + n] = f * (1.0f / 24.0f);
}

// ---------------------------------------------------------------------------
extern "C" void kernel_launch(void* const* d_in, const int* in_sizes, int n_in,
                              void* d_out, int out_size) {
    const float* x  = (const float*)d_in[0];   // [2,1024,3]
    const float* W1 = (const float*)d_in[1];   // [32,3]
    const float* b1 = (const float*)d_in[2];   // [32]
    const float* W2 = (const float*)d_in[3];   // [64,32]
    const float* b2 = (const float*)d_in[4];   // [64]
    float* out = (float*)d_out;                // [2,64,1024]

    gather_kernel<<<NQ / 8, 256>>>(x);
    mlp_kernel<<<(NQ * NVAR * 2) / 8, 256>>>(W1, b1, W2, b2);
    combine_kernel<<<(NQ * 64) / 256, 256>>>(b1, W2, b2, out);
}

// round 17
// speedup vs baseline: 1.1958x; 1.1958x over previous
#include <cuda_runtime.h>

// Problem constants (fixed by reference setup_inputs: B=2, N=1024, K=64, R=0.15)
#define NPTS   1024
#define NBATCH 2
#define NQ     (NBATCH * NPTS)     // 2048 queries
#define KNB    64
#define RADIUS2 0.0225f
#define NVAR   10                  // distinct nonzero diag variants

// Static device scratch (no allocation allowed)
__device__ float g_gp[NQ * 3 * KNB];        // SoA relative coords, zero-padded: [q][xyz][64]
__device__ int   g_cnt[NQ];                 // in-ball neighbor count per query
__device__ float g_m[NVAR * NQ * 64];       // per-variant per-query max, 64 ch

// diag variants: 4 full (weight 1 in combine), 6 single-axis (weight 2)
__device__ const float c_DX[NVAR] = { 1.f, 1.f,-1.f,-1.f,  1.f,-1.f, 0.f, 0.f, 0.f, 0.f };
__device__ const float c_DY[NVAR] = { 1.f,-1.f, 1.f,-1.f,  0.f, 0.f, 1.f,-1.f, 0.f, 0.f };
__device__ const float c_DZ[NVAR] = { 1.f,-1.f,-1.f, 1.f,  0.f, 0.f, 0.f, 0.f, 1.f,-1.f };

// ---- packed f32x2 helpers (Blackwell FFMA2: only reachable via PTX) -------
__device__ __forceinline__ unsigned long long ffma2(unsigned long long a,
                                                    unsigned long long b,
                                                    unsigned long long c) {
    unsigned long long d;
    asm("fma.rn.f32x2 %0, %1, %2, %3;" : "=l"(d) : "l"(a), "l"(b), "l"(c));
    return d;
}
__device__ __forceinline__ unsigned long long pack2(float lo, float hi) {
    unsigned long long d;
    asm("mov.b64 %0, {%1, %2};" : "=l"(d) : "f"(lo), "f"(hi));
    return d;
}
__device__ __forceinline__ float2 unpack2(unsigned long long v) {
    float lo, hi;
    asm("mov.b64 {%0, %1}, %2;" : "=f"(lo), "=f"(hi) : "l"(v));
    return make_float2(lo, hi);
}

// ---------------------------------------------------------------------------
// Kernel 1: ball gather — warp per query, ballot compaction (11.6us, kept).
// ---------------------------------------------------------------------------
__global__ void __launch_bounds__(256) gather_kernel(const float* __restrict__ x) {
    __shared__ float ysx[NPTS], ysy[NPTS], ysz[NPTS];
    int warp = threadIdx.x >> 5;
    int lane = threadIdx.x & 31;
    int q = blockIdx.x * 8 + warp;          // 256 blocks x 8 warps = 2048 queries
    int b = q >> 10;                        // all 8 warps of a block share batch
    const float* xb = x + b * NPTS * 3;
    for (int i = threadIdx.x; i < NPTS; i += 256) {
        ysx[i] = xb[i * 3 + 0];
        ysy[i] = xb[i * 3 + 1];
        ysz[i] = xb[i * 3 + 2];
    }
    __syncthreads();

    int n = q & 1023;
    float qx = ysx[n], qy = ysy[n], qz = ysz[n];
    float* gq = g_gp + q * (3 * KNB);

    int base = 0;
    for (int m0 = 0; m0 < NPTS; m0 += 32) {
        int m = m0 + lane;
        float dx = ysx[m] - qx;
        float dy = ysy[m] - qy;
        float dz = ysz[m] - qz;
        // match XLA rounding at the radius boundary: no FMA contraction
        float d2 = __fadd_rn(__fadd_rn(__fmul_rn(dx, dx), __fmul_rn(dy, dy)),
                             __fmul_rn(dz, dz));
        bool hit = (d2 <= RADIUS2);
        unsigned bal = __ballot_sync(0xffffffffu, hit);
        int pos = base + __popc(bal & ((1u << lane) - 1u));
        if (hit && pos < KNB) {
            gq[pos]           = dx;
            gq[KNB + pos]     = dy;
            gq[2 * KNB + pos] = dz;
        }
        base += __popc(bal);
    }
    int cnt = base < KNB ? base : KNB;
    for (int t = cnt + lane; t < KNB; t += 32) {
        gq[t] = 0.0f; gq[KNB + t] = 0.0f; gq[2 * KNB + t] = 0.0f;
    }

    if (base > KNB && lane == 0) {
        // exact rare path: keep the 64 smallest d2 (never fires on this data)
        float dds[KNB];
        int c = 0;
        for (int m = 0; m < NPTS; m++) {
            float dx = ysx[m] - qx, dy = ysy[m] - qy, dz = ysz[m] - qz;
            float d2 = __fadd_rn(__fadd_rn(__fmul_rn(dx, dx), __fmul_rn(dy, dy)),
                                 __fmul_rn(dz, dz));
            if (d2 <= RADIUS2) {
                if (c < KNB) {
                    dds[c] = d2;
                    gq[c] = dx; gq[KNB + c] = dy; gq[2 * KNB + c] = dz;
                    c++;
                } else {
                    float mx = -1.0f; int mi = 0;
                    for (int t = 0; t < KNB; t++)
                        if (dds[t] > mx) { mx = dds[t]; mi = t; }
                    if (d2 < mx) {
                        dds[mi] = d2;
                        gq[mi] = dx; gq[KNB + mi] = dy; gq[2 * KNB + mi] = dz;
                    }
                }
            }
        }
    }
    if (lane == 0) g_cnt[q] = cnt;
}

// ---------------------------------------------------------------------------
// Kernel 2: per-(query, variant) MLP + neighbor max. One warp per (q, v)
// (R14 layout: lane owns output channels lane and lane+32, full W2 in regs).
// NEW: neighbor count padded to a multiple of 4 — padded slots are exact
// duplicates of the self neighbor (g=0 -> c0), so the max is unchanged —
// and the j-loop is 4-way unrolled: 16 independent FFMA2 chains + 32
// independent LDS.128 in flight, hiding the 29-cycle LDS latency.
// ---------------------------------------------------------------------------
__global__ void __launch_bounds__(128, 4) mlp_kernel(const float* __restrict__ W1,
                                                     const float* __restrict__ b1,
                                                     const float* __restrict__ W2,
                                                     const float* __restrict__ b2) {
    __shared__ float4 sW1f4[32];                         // (w0,w1,w2,b1) per ch
    __shared__ __align__(16) float h1s[4][32][36];       // [warp][nbr][ch], padded

    int tid  = threadIdx.x;
    int lane = tid & 31;
    int wid  = tid >> 5;

    if (tid < 32)
        sW1f4[tid] = make_float4(W1[tid * 3 + 0], W1[tid * 3 + 1],
                                 W1[tid * 3 + 2], b1[tid]);
    __syncthreads();

    int w = blockIdx.x * 4 + wid;        // 0 .. 20479
    int q = w / NVAR;
    int v = w - q * NVAR;
    float sx = c_DX[v], sy = c_DY[v], sz = c_DZ[v];

    // W2 rows for output channels (lane, lane+32), as packed (c, c+1) pairs.
    unsigned long long w2a[16], w2b[16];
    {
        const ulonglong2* pa = reinterpret_cast<const ulonglong2*>(W2 + lane * 32);
        const ulonglong2* pb = reinterpret_cast<const ulonglong2*>(W2 + (lane + 32) * 32);
#pragma unroll
        for (int i = 0; i < 8; i++) {
            ulonglong2 ta = pa[i]; w2a[2 * i] = ta.x; w2a[2 * i + 1] = ta.y;
            ulonglong2 tb = pb[i]; w2b[2 * i] = tb.x; w2b[2 * i + 1] = tb.y;
        }
    }
    float bo0 = b2[lane], bo1 = b2[lane + 32];
    const unsigned long long bp0 = pack2(bo0, 0.0f);
    const unsigned long long bp1 = pack2(bo1, 0.0f);

    // pad count to multiple of 4: padded slots reproduce the self neighbor
    // (g=0 -> c0), already in the max set. cnt >= 1 always (self in ball).
    int cnt  = g_cnt[q];
    int pcnt = (cnt + 3) & ~3;           // 4..64
    const float* gq = g_gp + q * (3 * KNB);
    float (*hrow)[36] = h1s[wid];

    float m0 = 0.0f, m1 = 0.0f;          // relu outputs >= 0; self in set

    for (int j0 = 0; j0 < pcnt; j0 += 32) {
        // ---- phase 1: lane = neighbor (g_gp zero-padded, safe to read < 64)
        int jj = j0 + lane;
        float px = sx * gq[jj];
        float py = sy * gq[KNB + jj];
        float pz = sz * gq[2 * KNB + jj];
#pragma unroll
        for (int c = 0; c < 32; c += 4) {
            float4 hv;
            float4 w0 = sW1f4[c + 0];
            hv.x = fmaxf(fmaf(px, w0.x, fmaf(py, w0.y, fmaf(pz, w0.z, w0.w))), 0.0f);
            float4 w1r = sW1f4[c + 1];
            hv.y = fmaxf(fmaf(px, w1r.x, fmaf(py, w1r.y, fmaf(pz, w1r.z, w1r.w))), 0.0f);
            float4 w2r = sW1f4[c + 2];
            hv.z = fmaxf(fmaf(px, w2r.x, fmaf(py, w2r.y, fmaf(pz, w2r.z, w2r.w))), 0.0f);
            float4 w3r = sW1f4[c + 3];
            hv.w = fmaxf(fmaf(px, w3r.x, fmaf(py, w3r.y, fmaf(pz, w3r.z, w3r.w))), 0.0f);
            *reinterpret_cast<float4*>(&hrow[lane][c]) = hv;
        }
        __syncwarp();

        // ---- phase 2: lane = output-channel pair; 4 neighbors per step
        int jend = pcnt - j0; if (jend > 32) jend = 32;
        for (int j = 0; j < jend; j += 4) {
#pragma unroll
            for (int u = 0; u < 4; u++) {
                const ulonglong2* hp =
                    reinterpret_cast<const ulonglong2*>(&hrow[j + u][0]);
                unsigned long long acc0a = bp0, acc0b = 0ull;
                unsigned long long acc1a = bp1, acc1b = 0ull;
#pragma unroll
                for (int i = 0; i < 4; i++) {
                    ulonglong2 ha = hp[2 * i];     // h pairs (8i,8i+1),(8i+2,8i+3)
                    ulonglong2 hb = hp[2 * i + 1];
                    acc0a = ffma2(ha.x, w2a[4 * i + 0], acc0a);
                    acc1a = ffma2(ha.x, w2b[4 * i + 0], acc1a);
                    acc0b = ffma2(ha.y, w2a[4 * i + 1], acc0b);
                    acc1b = ffma2(ha.y, w2b[4 * i + 1], acc1b);
                    acc0a = ffma2(hb.x, w2a[4 * i + 2], acc0a);
                    acc1a = ffma2(hb.x, w2b[4 * i + 2], acc1a);
                    acc0b = ffma2(hb.y, w2a[4 * i + 3], acc0b);
                    acc1b = ffma2(hb.y, w2b[4 * i + 3], acc1b);
                }
                float2 s0a = unpack2(acc0a), s0b = unpack2(acc0b);
                float2 s1a = unpack2(acc1a), s1b = unpack2(acc1b);
                float r0 = (s0a.x + s0a.y) + (s0b.x + s0b.y);
                float r1 = (s1a.x + s1a.y) + (s1b.x + s1b.y);
                m0 = fmaxf(m0, fmaxf(r0, 0.0f));
                m1 = fmaxf(m1, fmaxf(r1, 0.0f));
            }
        }
        __syncwarp();
    }

    float* mo = g_m + (v * NQ + q) * 64;
    mo[lane]      = m0;
    mo[lane + 32] = m1;
}

// ---------------------------------------------------------------------------
// Kernel 3: combine. f[b,o,n] = (8*c0[o] + sum_v w_v * m[v,q,o]) / 24
// c0 = relu(W2 relu(b1) + b2): output of the 8 zero-diagonal rotations.
// ---------------------------------------------------------------------------
__global__ void __launch_bounds__(256) combine_kernel(const float* __restrict__ b1,
                                                      const float* __restrict__ W2,
                                                      const float* __restrict__ b2,
                                                      float* __restrict__ out) {
    __shared__ float h1b[32];
    __shared__ float c0s[64];
    int tid = threadIdx.x;
    if (tid < 32) h1b[tid] = fmaxf(b1[tid], 0.0f);
    __syncthreads();
    if (tid < 64) {
        float a = b2[tid];
#pragma unroll
        for (int c = 0; c < 32; c++) a = fmaf(W2[tid * 32 + c], h1b[c], a);
        c0s[tid] = 8.0f * fmaxf(a, 0.0f);
    }
    __syncthreads();

    const float WV[NVAR] = { 1.f, 1.f, 1.f, 1.f, 2.f, 2.f, 2.f, 2.f, 2.f, 2.f };

    int i = blockIdx.x * 256 + tid;      // 0 .. 131071 (= NQ*64)
    int q = i >> 6;
    int o = i & 63;
    float f = c0s[o];
#pragma unroll
    for (int v = 0; v < NVAR; v++)
        f += WV[v] * g_m[(v * NQ + q) * 64 + o];

    int b = q >> 10;
    int n = q & 1023;
    out[(b * 64 + o) * NPTS + n] = f * (1.0f / 24.0f);
}

// ---------------------------------------------------------------------------
extern "C" void kernel_launch(void* const* d_in, const int* in_sizes, int n_in,
                              void* d_out, int out_size) {
    const float* x  = (const float*)d_in[0];   // [2,1024,3]
    const float* W1 = (const float*)d_in[1];   // [32,3]
    const float* b1 = (const float*)d_in[2];   // [32]
    const float* W2 = (const float*)d_in[3];   // [64,32]
    const float* b2 = (const float*)d_in[4];   // [64]
    float* out = (float*)d_out;                // [2,64,1024]

    gather_kernel<<<NQ / 8, 256>>>(x);
    mlp_kernel<<<(NQ * NVAR) / 4, 128>>>(W1, b1, W2, b2);
    combine_kernel<<<(NQ * 64) / 256, 256>>>(b1, W2, b2, out);
}